// round 15
// baseline (speedup 1.0000x reference)
#include <cuda_runtime.h>
#include <math_constants.h>
#include <cstdint>

#define B_PAT 4096
#define N_DIS 10000
#define DIM   256
#define BLK   16                 // ranks per block
#define NB    640                // blocks
#define NRANK (NB*BLK)           // 10240 padded ranks
#define L2EF  1.4426950408889634f
#define LEAKY 0.2f

typedef uint32_t u32;
typedef unsigned long long ull;

// ---------------- device globals (no allocation) ----------------
__device__ float g_sp[B_PAT];
__device__ float g_sn[N_DIS];
__device__ int   g_rank[N_DIS];
__device__ int   g_ord[NRANK];          // rank -> node (pads unwritten, guarded)
__device__ float g_snsort[NRANK];       // sorted sn (ranks < N_DIS)
__device__ int   g_kb[B_PAT];           // per-patient threshold rank
__device__ float g_B1[NB][DIM], g_B2[NB][DIM];       // block sums
__device__ float g_Off1[NB][DIM], g_Off2[NB][DIM];   // block suffix/prefix offsets
__device__ float g_sufs[NRANK];         // scalar suffix sums of F1 (incl r)
__device__ float g_pres[NRANK];         // scalar prefix sums of F2 (excl r)

__device__ __forceinline__ float ex2(float x) {
    float r; asm("ex2.approx.ftz.f32 %0, %1;" : "=f"(r) : "f"(x)); return r;
}
__device__ __forceinline__ unsigned enc_f(float f) {
    unsigned u = __float_as_uint(f);
    return (u & 0x80000000u) ? ~u : (u | 0x80000000u);
}

// ---------------- kernel 1: sp, sn dot products (+ zero ranks) ----------------
__global__ __launch_bounds__(256) void k_scores(
    const float* __restrict__ pf, const float* __restrict__ dn,
    const float* __restrict__ ak)
{
    int tid  = threadIdx.x;
    int lane = tid & 31;
    int gw   = blockIdx.x * 8 + (tid >> 5);

    float v = 0.0f;
    if (gw < B_PAT) {
        const float4* r = (const float4*)(pf + (size_t)gw * DIM);
        const float4* w = (const float4*)ak;
        #pragma unroll
        for (int k = 0; k < 2; k++) {
            float4 x  = r[lane * 2 + k];
            float4 ww = __ldg(&w[lane * 2 + k]);
            v += x.x * ww.x + x.y * ww.y + x.z * ww.z + x.w * ww.w;
        }
    } else if (gw < B_PAT + N_DIS) {
        const float4* r = (const float4*)(dn + (size_t)(gw - B_PAT) * DIM);
        const float4* w = (const float4*)(ak + DIM);
        #pragma unroll
        for (int k = 0; k < 2; k++) {
            float4 x  = r[lane * 2 + k];
            float4 ww = __ldg(&w[lane * 2 + k]);
            v += x.x * ww.x + x.y * ww.y + x.z * ww.z + x.w * ww.w;
        }
    }
    #pragma unroll
    for (int o = 16; o; o >>= 1) v += __shfl_xor_sync(0xffffffffu, v, o);

    if (lane == 0) {
        if (gw < B_PAT) {
            g_sp[gw] = v;
        } else if (gw < B_PAT + N_DIS) {
            g_sn[gw - B_PAT]   = v;
            g_rank[gw - B_PAT] = 0;
        }
    }
}

// ---------------- kernel 2: counting rank via packed u64 keys ----------------
// grid (40, 8): node group x domain split. Deterministic integer atomics.
__global__ __launch_bounds__(256) void k_rank()
{
    __shared__ ull sm[1252];
    const int tid   = threadIdx.x;
    const int n     = blockIdx.x * 256 + tid;
    const int mbase = blockIdx.y * 1250;

    for (int i = tid; i < 1252; i += 256) {
        ull key = ~0ULL;                       // pad: never < mykey
        if (i < 1250) {
            int m = mbase + i;
            key = ((ull)enc_f(g_sn[m]) << 32) | (u32)m;
        }
        sm[i] = key;
    }
    __syncthreads();

    const bool valid = (n < N_DIS);
    const ull mykey = valid ? (((ull)enc_f(g_sn[n]) << 32) | (u32)n) : 0ULL;
    int cnt = 0;
    #pragma unroll 8
    for (int i = 0; i < 1252; i++) cnt += (sm[i] < mykey);
    if (valid) atomicAdd(&g_rank[n], cnt);
}

// ---------------- kernel 3: scatter into sorted order ----------------
__global__ __launch_bounds__(256) void k_scat()
{
    int n = blockIdx.x * 256 + threadIdx.x;
    if (n < N_DIS) {
        int r = g_rank[n];
        g_ord[r]    = n;
        g_snsort[r] = g_sn[n];
    }
}

// ---------------- kernel 4: block sums of F1*dn and F2*dn ----------------
// grid NB (640), 256 threads (one per dim), 16 ranks per block.
__global__ __launch_bounds__(256) void k_scanA(const float* __restrict__ dn)
{
    __shared__ float sF1[BLK], sF2[BLK];
    __shared__ int   sOrd[BLK];
    const int tid = threadIdx.x;
    const int j   = blockIdx.x;

    if (tid < BLK) {
        int r = j * BLK + tid;
        float f1 = 0.0f, f2 = 0.0f; int o = 0;
        if (r < N_DIS) {
            float key = g_snsort[r];
            f1 = ex2(key * L2EF);
            f2 = ex2(key * (LEAKY * L2EF));
            o  = g_ord[r];
        }
        sF1[tid] = f1; sF2[tid] = f2; sOrd[tid] = o;
    }
    __syncthreads();

    const int d = tid;
    float s1 = 0.0f, s2 = 0.0f;
    #pragma unroll
    for (int i = 0; i < BLK; i++) {
        float v = __ldg(&dn[(size_t)sOrd[i] * DIM + d]);   // f=0 for pads
        s1 += sF1[i] * v;
        s2 += sF2[i] * v;
    }
    g_B1[j][d] = s1;
    g_B2[j][d] = s2;
}

// ---------------- kernel 5: block offsets (vector) + scalar rank scans ----------------
// 1 CTA, 256 threads.
__global__ __launch_bounds__(256) void k_scanB()
{
    const int tid = threadIdx.x;

    // vector block offsets: Off1[j] = sum of blocks AFTER j; Off2[j] = BEFORE j
    {
        const int d = tid;
        float run = 0.0f;
        for (int j = NB - 1; j >= 0; j--) { g_Off1[j][d] = run; run += g_B1[j][d]; }
        run = 0.0f;
        for (int j = 0; j < NB; j++)      { g_Off2[j][d] = run; run += g_B2[j][d]; }
    }

    // scalar scans over ranks: thread t owns ranks [t*40, t*40+40)
    float t1 = 0.0f, t2 = 0.0f;
    for (int i = 0; i < 40; i++) {
        int r = tid * 40 + i;
        if (r < N_DIS) {
            float key = g_snsort[r];
            t1 += ex2(key * L2EF);
            t2 += ex2(key * (LEAKY * L2EF));
        }
    }
    __shared__ float p1[256], p2[256], o1[256], o2[256];
    p1[tid] = t1; p2[tid] = t2;
    __syncthreads();
    if (tid == 0) {
        float r1 = 0.0f;
        for (int t = 255; t >= 0; t--) { o1[t] = r1; r1 += p1[t]; }
        float r2 = 0.0f;
        for (int t = 0; t < 256; t++)  { o2[t] = r2; r2 += p2[t]; }
    }
    __syncthreads();

    float run1 = o1[tid];
    for (int i = 39; i >= 0; i--) {
        int r = tid * 40 + i;
        if (r < N_DIS) run1 += ex2(g_snsort[r] * L2EF);
        g_sufs[r] = run1;                       // suffix incl. r
    }
    float run2 = o2[tid];
    for (int i = 0; i < 40; i++) {
        int r = tid * 40 + i;
        g_pres[r] = run2;                       // prefix excl. r
        if (r < N_DIS) run2 += ex2(g_snsort[r] * (LEAKY * L2EF));
    }
}

// ---------------- kernel 6: per-patient threshold rank (binary search) ----------------
__global__ __launch_bounds__(256) void k_thr()
{
    int b = blockIdx.x * 256 + threadIdx.x;
    if (b >= B_PAT) return;
    float th = -g_sp[b];
    int lo = 0, hi = N_DIS;
    while (lo < hi) {
        int mid = (lo + hi) >> 1;
        if (__ldg(&g_snsort[mid]) < th) lo = mid + 1; else hi = mid;
    }
    g_kb[b] = lo;                               // 0..N_DIS
}

// ---------------- kernel 7: combine (block offsets + <=16-row correction) ----------------
// grid B_PAT/4, 256 threads: 4 patients x 64 lanes (4 dims each).
__global__ __launch_bounds__(256) void k_fin(
    const float* __restrict__ pf, const float* __restrict__ dn,
    float* __restrict__ out)
{
    __shared__ float sF1[4][BLK], sF2[4][BLK];
    __shared__ int   sOrd[4][BLK];
    __shared__ int   s_k[4];
    const int tid = threadIdx.x;

    if (tid < 4) s_k[tid] = g_kb[blockIdx.x * 4 + tid];
    __syncthreads();

    if (tid < 64) {
        int p = tid >> 4, i = tid & 15;
        int r = (s_k[p] & ~(BLK - 1)) + i;      // block start + i
        float f1 = 0.0f, f2 = 0.0f; int o = 0;
        if (r < N_DIS) {
            float key = __ldg(&g_snsort[r]);
            f1 = ex2(key * L2EF);
            f2 = ex2(key * (LEAKY * L2EF));
            o  = __ldg(&g_ord[r]);
        }
        sF1[p][i] = f1; sF2[p][i] = f2; sOrd[p][i] = o;
    }
    __syncthreads();

    const int pat = tid >> 6;
    const int l   = tid & 63;
    const int b   = blockIdx.x * 4 + pat;
    const int k   = s_k[pat];
    const int j   = k >> 4;
    const int rem = k & (BLK - 1);

    const float sp = g_sp[b];
    const float E1 = ex2(sp * L2EF);
    const float E2 = ex2(sp * (LEAKY * L2EF));
    const float den = E1 * __ldg(&g_sufs[k]) + E2 * __ldg(&g_pres[k]);
    const float inv = 1.0f / den;

    const int d0 = l * 4;
    float4 s1 = make_float4(0.f, 0.f, 0.f, 0.f);
    float4 s2 = make_float4(0.f, 0.f, 0.f, 0.f);
    #pragma unroll
    for (int i = 0; i < BLK; i++) {
        float4 v = *(const float4*)&dn[(size_t)sOrd[pat][i] * DIM + d0];
        if (i >= rem) {                         // rank >= k: branch-1 (suffix)
            float f1 = sF1[pat][i];
            s1.x += f1 * v.x; s1.y += f1 * v.y; s1.z += f1 * v.z; s1.w += f1 * v.w;
        } else {                                // rank < k: branch-2 (prefix)
            float f2 = sF2[pat][i];
            s2.x += f2 * v.x; s2.y += f2 * v.y; s2.z += f2 * v.z; s2.w += f2 * v.w;
        }
    }
    float4 off1 = *(const float4*)&g_Off1[j][d0];
    float4 off2 = *(const float4*)&g_Off2[j][d0];
    float4 x    = *(const float4*)&pf[(size_t)b * DIM + d0];
    float4 o;
    o.x = x.x + (E1 * (off1.x + s1.x) + E2 * (off2.x + s2.x)) * inv;
    o.y = x.y + (E1 * (off1.y + s1.y) + E2 * (off2.y + s2.y)) * inv;
    o.z = x.z + (E1 * (off1.z + s1.z) + E2 * (off2.z + s2.z)) * inv;
    o.w = x.w + (E1 * (off1.w + s1.w) + E2 * (off2.w + s2.w)) * inv;
    *(float4*)&out[(size_t)b * DIM + d0] = o;
}

// ---------------- launch ----------------
extern "C" void kernel_launch(void* const* d_in, const int* in_sizes, int n_in,
                              void* d_out, int out_size)
{
    const float* pf = (const float*)d_in[0];   // [4096, 256]
    const float* dn = (const float*)d_in[1];   // [10000, 256]
    const float* ak = (const float*)d_in[2];   // [512, 1]
    float* out = (float*)d_out;

    k_scores<<<(B_PAT + N_DIS) / 8, 256>>>(pf, dn, ak);
    k_rank <<<dim3(40, 8), 256>>>();
    k_scat <<<40, 256>>>();
    k_scanA<<<NB, 256>>>(dn);
    k_scanB<<<1, 256>>>();
    k_thr  <<<B_PAT / 256, 256>>>();
    k_fin  <<<B_PAT / 4, 256>>>(pf, dn, out);
}

// round 16
// speedup vs baseline: 4.8449x; 4.8449x over previous
#include <cuda_runtime.h>
#include <math_constants.h>
#include <cstdint>

#define B_PAT 4096
#define N_DIS 10000
#define DIM   256
#define BLK   16                 // ranks per block
#define NB    640                // blocks
#define NRANK (NB*BLK)           // 10240 padded ranks
#define L2EF  1.4426950408889634f
#define LEAKY 0.2f

typedef uint32_t u32;
typedef unsigned long long ull;

// ---------------- device globals (no allocation) ----------------
__device__ float g_sp[B_PAT];
__device__ float g_sn[N_DIS];
__device__ int   g_rank[N_DIS];
__device__ int   g_ord[NRANK];          // rank -> node (pads unwritten, guarded)
__device__ float g_snsort[NRANK];       // sorted sn (ranks < N_DIS)
__device__ int   g_kb[B_PAT];           // per-patient threshold rank
__device__ float g_B1[NB][DIM], g_B2[NB][DIM];       // block sums
__device__ float g_Off1[NB][DIM], g_Off2[NB][DIM];   // block suffix/prefix offsets
__device__ float g_sufs[NRANK + 1];     // scalar suffix sums of F1 (incl r)
__device__ float g_pres[NRANK + 1];     // scalar prefix sums of F2 (excl r)

__device__ __forceinline__ float ex2(float x) {
    float r; asm("ex2.approx.ftz.f32 %0, %1;" : "=f"(r) : "f"(x)); return r;
}
__device__ __forceinline__ unsigned enc_f(float f) {
    unsigned u = __float_as_uint(f);
    return (u & 0x80000000u) ? ~u : (u | 0x80000000u);
}

// ---------------- kernel 1: sp, sn dot products (+ zero ranks) ----------------
__global__ __launch_bounds__(256) void k_scores(
    const float* __restrict__ pf, const float* __restrict__ dn,
    const float* __restrict__ ak)
{
    int tid  = threadIdx.x;
    int lane = tid & 31;
    int gw   = blockIdx.x * 8 + (tid >> 5);

    float v = 0.0f;
    if (gw < B_PAT) {
        const float4* r = (const float4*)(pf + (size_t)gw * DIM);
        const float4* w = (const float4*)ak;
        #pragma unroll
        for (int k = 0; k < 2; k++) {
            float4 x  = r[lane * 2 + k];
            float4 ww = __ldg(&w[lane * 2 + k]);
            v += x.x * ww.x + x.y * ww.y + x.z * ww.z + x.w * ww.w;
        }
    } else if (gw < B_PAT + N_DIS) {
        const float4* r = (const float4*)(dn + (size_t)(gw - B_PAT) * DIM);
        const float4* w = (const float4*)(ak + DIM);
        #pragma unroll
        for (int k = 0; k < 2; k++) {
            float4 x  = r[lane * 2 + k];
            float4 ww = __ldg(&w[lane * 2 + k]);
            v += x.x * ww.x + x.y * ww.y + x.z * ww.z + x.w * ww.w;
        }
    }
    #pragma unroll
    for (int o = 16; o; o >>= 1) v += __shfl_xor_sync(0xffffffffu, v, o);

    if (lane == 0) {
        if (gw < B_PAT) {
            g_sp[gw] = v;
        } else if (gw < B_PAT + N_DIS) {
            g_sn[gw - B_PAT]   = v;
            g_rank[gw - B_PAT] = 0;
        }
    }
}

// ---------------- kernel 2: counting rank via packed u64 keys ----------------
__global__ __launch_bounds__(256) void k_rank()
{
    __shared__ ull sm[1252];
    const int tid   = threadIdx.x;
    const int n     = blockIdx.x * 256 + tid;
    const int mbase = blockIdx.y * 1250;

    for (int i = tid; i < 1252; i += 256) {
        ull key = ~0ULL;                       // pad: never < mykey
        if (i < 1250) {
            int m = mbase + i;
            key = ((ull)enc_f(g_sn[m]) << 32) | (u32)m;
        }
        sm[i] = key;
    }
    __syncthreads();

    const bool valid = (n < N_DIS);
    const ull mykey = valid ? (((ull)enc_f(g_sn[n]) << 32) | (u32)n) : 0ULL;
    int cnt = 0;
    #pragma unroll 8
    for (int i = 0; i < 1252; i++) cnt += (sm[i] < mykey);
    if (valid) atomicAdd(&g_rank[n], cnt);
}

// ---------------- kernel 3: scatter into sorted order ----------------
__global__ __launch_bounds__(256) void k_scat()
{
    int n = blockIdx.x * 256 + threadIdx.x;
    if (n < N_DIS) {
        int r = g_rank[n];
        g_ord[r]    = n;
        g_snsort[r] = g_sn[n];
    }
}

// ---------------- kernel 4: block sums of F1*dn and F2*dn ----------------
__global__ __launch_bounds__(256) void k_scanA(const float* __restrict__ dn)
{
    __shared__ float sF1[BLK], sF2[BLK];
    __shared__ int   sOrd[BLK];
    const int tid = threadIdx.x;
    const int j   = blockIdx.x;

    if (tid < BLK) {
        int r = j * BLK + tid;
        float f1 = 0.0f, f2 = 0.0f; int o = 0;
        if (r < N_DIS) {
            float key = g_snsort[r];
            f1 = ex2(key * L2EF);
            f2 = ex2(key * (LEAKY * L2EF));
            o  = g_ord[r];
        }
        sF1[tid] = f1; sF2[tid] = f2; sOrd[tid] = o;
    }
    __syncthreads();

    const int d = tid;
    float s1 = 0.0f, s2 = 0.0f;
    #pragma unroll
    for (int i = 0; i < BLK; i++) {
        float v = __ldg(&dn[(size_t)sOrd[i] * DIM + d]);
        s1 += sF1[i] * v;
        s2 += sF2[i] * v;
    }
    g_B1[j][d] = s1;
    g_B2[j][d] = s2;
}

// ---------------- kernel 5: per-dim parallel scan of block sums ----------------
// grid DIM (256), block 128. thread t owns j in [t*5, t*5+5).
__global__ __launch_bounds__(128) void k_scanB()
{
    __shared__ float sB1[NB], sB2[NB];
    __shared__ float wtot1[4], wtot2[4], woff1[4], woff2[4];
    const int tid  = threadIdx.x;
    const int lane = tid & 31;
    const int wrp  = tid >> 5;
    const int d    = blockIdx.x;

    for (int j = tid; j < NB; j += 128) {
        sB1[j] = g_B1[j][d];
        sB2[j] = g_B2[j][d];
    }
    __syncthreads();

    // local sums over owned 5
    float s1 = 0.0f, s2 = 0.0f;
    #pragma unroll
    for (int i = 0; i < 5; i++) { s1 += sB1[tid * 5 + i]; s2 += sB2[tid * 5 + i]; }

    // warp inclusive scan
    float v1 = s1, v2 = s2;
    #pragma unroll
    for (int o = 1; o < 32; o <<= 1) {
        float n1 = __shfl_up_sync(0xffffffffu, v1, o);
        float n2 = __shfl_up_sync(0xffffffffu, v2, o);
        if (lane >= o) { v1 += n1; v2 += n2; }
    }
    if (lane == 31) { wtot1[wrp] = v1; wtot2[wrp] = v2; }
    __syncthreads();
    if (tid == 0) {
        float r1 = 0.0f, r2 = 0.0f;
        #pragma unroll
        for (int w = 0; w < 4; w++) {
            woff1[w] = r1; r1 += wtot1[w];
            woff2[w] = r2; r2 += wtot2[w];
        }
        wtot1[0] = r1;          // reuse slot 0 as grand total
        wtot2[0] = r2;
    }
    __syncthreads();

    const float T1 = wtot1[0], T2 = wtot2[0];
    float p1 = woff1[wrp] + (v1 - s1);          // exclusive prefix of thread
    float p2 = woff2[wrp] + (v2 - s2);
    #pragma unroll
    for (int i = 0; i < 5; i++) {
        int j = tid * 5 + i;
        float b1 = sB1[j], b2 = sB2[j];
        g_Off1[j][d] = T1 - p1 - b1;            // sum of blocks AFTER j
        g_Off2[j][d] = p2;                      // sum of blocks BEFORE j
        p1 += b1; p2 += b2;
    }
}

// ---------------- kernel 6: scalar rank scans (parallel) ----------------
// 1 CTA, 1024 threads; thread t owns ranks [t*10, t*10+10).
__global__ __launch_bounds__(1024) void k_scanS()
{
    __shared__ float wtot1[32], wtot2[32], woff1[32], woff2[32];
    __shared__ float gt1, gt2;
    const int tid  = threadIdx.x;
    const int lane = tid & 31;
    const int wrp  = tid >> 5;

    float f1[10], f2[10];
    float s1 = 0.0f, s2 = 0.0f;
    #pragma unroll
    for (int i = 0; i < 10; i++) {
        int r = tid * 10 + i;
        float a = 0.0f, b = 0.0f;
        if (r < N_DIS) {
            float key = g_snsort[r];
            a = ex2(key * L2EF);
            b = ex2(key * (LEAKY * L2EF));
        }
        f1[i] = a; f2[i] = b;
        s1 += a; s2 += b;
    }

    float v1 = s1, v2 = s2;
    #pragma unroll
    for (int o = 1; o < 32; o <<= 1) {
        float n1 = __shfl_up_sync(0xffffffffu, v1, o);
        float n2 = __shfl_up_sync(0xffffffffu, v2, o);
        if (lane >= o) { v1 += n1; v2 += n2; }
    }
    if (lane == 31) { wtot1[wrp] = v1; wtot2[wrp] = v2; }
    __syncthreads();
    if (wrp == 0) {
        float a = wtot1[lane], b = wtot2[lane];
        float x1 = a, x2 = b;
        #pragma unroll
        for (int o = 1; o < 32; o <<= 1) {
            float n1 = __shfl_up_sync(0xffffffffu, x1, o);
            float n2 = __shfl_up_sync(0xffffffffu, x2, o);
            if (lane >= o) { x1 += n1; x2 += n2; }
        }
        woff1[lane] = x1 - a;                   // exclusive
        woff2[lane] = x2 - b;
        if (lane == 31) { gt1 = x1; gt2 = x2; }
    }
    __syncthreads();

    const float T1 = gt1;
    float p1 = woff1[wrp] + (v1 - s1);          // exclusive prefix of F1
    float p2 = woff2[wrp] + (v2 - s2);          // exclusive prefix of F2
    #pragma unroll
    for (int i = 0; i < 10; i++) {
        int r = tid * 10 + i;
        g_sufs[r] = T1 - p1;                    // suffix incl. r
        g_pres[r] = p2;                         // prefix excl. r
        p1 += f1[i]; p2 += f2[i];
    }
    if (tid == 1023) { g_sufs[NRANK] = 0.0f; g_pres[NRANK] = p2; }
}

// ---------------- kernel 7: per-patient threshold rank ----------------
__global__ __launch_bounds__(256) void k_thr()
{
    int b = blockIdx.x * 256 + threadIdx.x;
    if (b >= B_PAT) return;
    float th = -g_sp[b];
    int lo = 0, hi = N_DIS;
    while (lo < hi) {
        int mid = (lo + hi) >> 1;
        if (__ldg(&g_snsort[mid]) < th) lo = mid + 1; else hi = mid;
    }
    g_kb[b] = lo;
}

// ---------------- kernel 8: combine (block offsets + <=16-row correction) ----------------
__global__ __launch_bounds__(256) void k_fin(
    const float* __restrict__ pf, const float* __restrict__ dn,
    float* __restrict__ out)
{
    __shared__ float sF1[4][BLK], sF2[4][BLK];
    __shared__ int   sOrd[4][BLK];
    __shared__ int   s_k[4];
    const int tid = threadIdx.x;

    if (tid < 4) s_k[tid] = g_kb[blockIdx.x * 4 + tid];
    __syncthreads();

    if (tid < 64) {
        int p = tid >> 4, i = tid & 15;
        int r = (s_k[p] & ~(BLK - 1)) + i;
        float f1 = 0.0f, f2 = 0.0f; int o = 0;
        if (r < N_DIS) {
            float key = __ldg(&g_snsort[r]);
            f1 = ex2(key * L2EF);
            f2 = ex2(key * (LEAKY * L2EF));
            o  = __ldg(&g_ord[r]);
        }
        sF1[p][i] = f1; sF2[p][i] = f2; sOrd[p][i] = o;
    }
    __syncthreads();

    const int pat = tid >> 6;
    const int l   = tid & 63;
    const int b   = blockIdx.x * 4 + pat;
    const int k   = s_k[pat];
    const int j   = k >> 4;
    const int rem = k & (BLK - 1);

    const float sp = g_sp[b];
    const float E1 = ex2(sp * L2EF);
    const float E2 = ex2(sp * (LEAKY * L2EF));
    const float den = E1 * __ldg(&g_sufs[k]) + E2 * __ldg(&g_pres[k]);
    const float inv = 1.0f / den;

    const int d0 = l * 4;
    float4 s1 = make_float4(0.f, 0.f, 0.f, 0.f);
    float4 s2 = make_float4(0.f, 0.f, 0.f, 0.f);
    #pragma unroll
    for (int i = 0; i < BLK; i++) {
        float4 v = *(const float4*)&dn[(size_t)sOrd[pat][i] * DIM + d0];
        if (i >= rem) {
            float f1 = sF1[pat][i];
            s1.x += f1 * v.x; s1.y += f1 * v.y; s1.z += f1 * v.z; s1.w += f1 * v.w;
        } else {
            float f2 = sF2[pat][i];
            s2.x += f2 * v.x; s2.y += f2 * v.y; s2.z += f2 * v.z; s2.w += f2 * v.w;
        }
    }
    // j == NB only possible if k == NRANK (impossible: k <= N_DIS < NRANK)
    float4 off1 = *(const float4*)&g_Off1[j][d0];
    float4 off2 = *(const float4*)&g_Off2[j][d0];
    float4 x    = *(const float4*)&pf[(size_t)b * DIM + d0];
    float4 o;
    o.x = x.x + (E1 * (off1.x + s1.x) + E2 * (off2.x + s2.x)) * inv;
    o.y = x.y + (E1 * (off1.y + s1.y) + E2 * (off2.y + s2.y)) * inv;
    o.z = x.z + (E1 * (off1.z + s1.z) + E2 * (off2.z + s2.z)) * inv;
    o.w = x.w + (E1 * (off1.w + s1.w) + E2 * (off2.w + s2.w)) * inv;
    *(float4*)&out[(size_t)b * DIM + d0] = o;
}

// ---------------- launch ----------------
extern "C" void kernel_launch(void* const* d_in, const int* in_sizes, int n_in,
                              void* d_out, int out_size)
{
    const float* pf = (const float*)d_in[0];   // [4096, 256]
    const float* dn = (const float*)d_in[1];   // [10000, 256]
    const float* ak = (const float*)d_in[2];   // [512, 1]
    float* out = (float*)d_out;

    k_scores<<<(B_PAT + N_DIS) / 8, 256>>>(pf, dn, ak);
    k_rank <<<dim3(40, 8), 256>>>();
    k_scat <<<40, 256>>>();
    k_scanA<<<NB, 256>>>(dn);
    k_scanB<<<DIM, 128>>>();
    k_scanS<<<1, 1024>>>();
    k_thr  <<<B_PAT / 256, 256>>>();
    k_fin  <<<B_PAT / 4, 256>>>(pf, dn, out);
}